// round 11
// baseline (speedup 1.0000x reference)
#include <cuda_runtime.h>
#include <cuda_bf16.h>
#include <cstdint>

// ---------------------------------------------------------------------------
// 2-layer bidirectional GRU. B=32, S=2048, D=256, H=256, gates=768.
//   gx = X @ W_ih^T + b_ih      (parallel GEMM)
//   step: gh = h @ W_hh^T + b_hh; r=sig(xr+hr) z=sig(xz+hz)
//         n=tanh(xn+r*hn); h' = (1-z)*n + z*h
// Scan: 16 groups (2 dirs x 8 batch-chunks of 4), each an 8-CTA cluster.
// CTA rank owns 32 j's (96 W_hh rows in smem). 256 threads: half = tid>>7
// computes the k-half partial of all three gate dots for element (b, j);
// halves combined via one smem float4 exchange; half 0 applies gates and
// scatters h' to every cluster CTA via st.shared::cluster. One
// barrier.cluster per step. Dot fully unrolled for deep LDS pipelining.
// ---------------------------------------------------------------------------

#define S_LEN  2048
#define NBATCH 32
#define HID    256
#define G3     768
#define OUTW   512
#define BC     4          // batches per group
#define CSIZE  8          // CTAs per cluster
#define JPC    32         // j's per CTA
#define HPAD   260        // padded row stride (floats)
#define SCTH   256

#define SW_FLOATS (3 * JPC * HPAD)                   // 24960
#define SH_FLOATS (2 * BC * HPAD)                    // 2080
#define SR_FLOATS (128 * 4)                          // 512
#define SMEM_BYTES ((SW_FLOATS + SH_FLOATS + SR_FLOATS) * 4)

__device__ float g_gx[(size_t)NBATCH * S_LEN * G3];
__device__ float g_out0[(size_t)NBATCH * S_LEN * OUTW];

// ---- f32x2 helpers --------------------------------------------------------
__device__ __forceinline__ void fma2(uint64_t& d, uint64_t a, uint64_t b) {
    asm("fma.rn.f32x2 %0, %1, %2, %0;" : "+l"(d) : "l"(a), "l"(b));
}
__device__ __forceinline__ uint64_t pk(float lo, float hi) {
    uint64_t r; asm("mov.b64 %0, {%1, %2};" : "=l"(r) : "f"(lo), "f"(hi)); return r;
}
__device__ __forceinline__ float upks(uint64_t v) {
    float lo, hi; asm("mov.b64 {%0, %1}, %2;" : "=f"(lo), "=f"(hi) : "l"(v));
    return lo + hi;
}
__device__ __forceinline__ float fsig(float x) {
    return __fdividef(1.f, 1.f + __expf(-x));
}
__device__ __forceinline__ float ftanh(float x) {
    return 1.f - __fdividef(2.f, __expf(2.f * x) + 1.f);
}

// ---------------------------------------------------------------------------
// GEMM (unchanged from R8): C[m][n] = sum_k A[m][k]*W[n][k] + bias[n]
// ---------------------------------------------------------------------------
__global__ void __launch_bounds__(256) k_gemm(
    const float* __restrict__ Aext, const float* __restrict__ W,
    const float* __restrict__ bias, int K, int useInternalA)
{
    __shared__ float As[8][132];
    __shared__ float Bs[8][68];

    const float* A = useInternalA ? &g_out0[0] : Aext;
    float* C = &g_gx[0];

    const int tid = threadIdx.x;
    const int bm = blockIdx.x, bn = blockIdx.y;
    const int tx = tid & 15, ty = tid >> 4;

    const int lr = tid >> 1, lq = (tid & 1) * 4;
    const float* Ap = A + (size_t)(bm * 128 + lr) * K + lq;
    const float* Bp = W + (size_t)(bn * 64 + (lr & 63)) * K + lq;
    const bool loadB = (tid < 128);

    uint64_t acc[8][4];
#pragma unroll
    for (int i = 0; i < 8; ++i)
#pragma unroll
        for (int j = 0; j < 4; ++j) acc[i][j] = 0ull;

    float4 av = *(const float4*)Ap;
    float4 bv = loadB ? *(const float4*)Bp : make_float4(0.f, 0.f, 0.f, 0.f);

    for (int kt = 0; kt < K; kt += 8) {
        __syncthreads();
        As[lq + 0][lr] = av.x; As[lq + 1][lr] = av.y;
        As[lq + 2][lr] = av.z; As[lq + 3][lr] = av.w;
        if (loadB) {
            Bs[lq + 0][lr] = bv.x; Bs[lq + 1][lr] = bv.y;
            Bs[lq + 2][lr] = bv.z; Bs[lq + 3][lr] = bv.w;
        }
        __syncthreads();
        if (kt + 8 < K) {
            av = *(const float4*)(Ap + kt + 8);
            if (loadB) bv = *(const float4*)(Bp + kt + 8);
        }
#pragma unroll
        for (int k2 = 0; k2 < 4; ++k2) {
            float4 aL0 = *(const float4*)&As[2 * k2][ty * 8];
            float4 aH0 = *(const float4*)&As[2 * k2][ty * 8 + 4];
            float4 aL1 = *(const float4*)&As[2 * k2 + 1][ty * 8];
            float4 aH1 = *(const float4*)&As[2 * k2 + 1][ty * 8 + 4];
            float4 b0  = *(const float4*)&Bs[2 * k2][tx * 4];
            float4 b1  = *(const float4*)&Bs[2 * k2 + 1][tx * 4];
            uint64_t am[8], bb[4];
            am[0] = pk(aL0.x, aL1.x); am[1] = pk(aL0.y, aL1.y);
            am[2] = pk(aL0.z, aL1.z); am[3] = pk(aL0.w, aL1.w);
            am[4] = pk(aH0.x, aH1.x); am[5] = pk(aH0.y, aH1.y);
            am[6] = pk(aH0.z, aH1.z); am[7] = pk(aH0.w, aH1.w);
            bb[0] = pk(b0.x, b1.x);   bb[1] = pk(b0.y, b1.y);
            bb[2] = pk(b0.z, b1.z);   bb[3] = pk(b0.w, b1.w);
#pragma unroll
            for (int i = 0; i < 8; ++i)
#pragma unroll
                for (int j = 0; j < 4; ++j) fma2(acc[i][j], am[i], bb[j]);
        }
    }

    const int n0 = bn * 64 + tx * 4;
    float4 b4 = *(const float4*)&bias[n0];
#pragma unroll
    for (int i = 0; i < 8; ++i) {
        size_t m = (size_t)bm * 128 + ty * 8 + i;
        float4 o;
        o.x = upks(acc[i][0]) + b4.x;
        o.y = upks(acc[i][1]) + b4.y;
        o.z = upks(acc[i][2]) + b4.z;
        o.w = upks(acc[i][3]) + b4.w;
        *(float4*)&C[m * G3 + n0] = o;
    }
}

// ---------------------------------------------------------------------------
// Cluster scan. Grid = 128 CTAs x 256 threads, cluster (8,1,1).
//   group gcl = bid>>3 (dir = gcl&1, b0 = (gcl>>1)*4), rank = bid&7.
//   half = tid>>7 selects k-half; li = tid&127: b = (li&31)>>3,
//   jl = (li>>5)*8 + (li&7), jg = rank*32 + jl.
// ---------------------------------------------------------------------------
__global__ void __launch_bounds__(SCTH, 1) __cluster_dims__(CSIZE, 1, 1)
k_scan(const float* __restrict__ Whh, const float* __restrict__ bhh,
       float* __restrict__ dout, int layer, int write_hn)
{
    extern __shared__ float smem[];
    float*  sW   = smem;                           // [3][JPC][HPAD]
    float*  sh   = smem + SW_FLOATS;               // [2][BC][HPAD]
    float4* sred = (float4*)(smem + SW_FLOATS + SH_FLOATS);  // [128]

    const int tid = threadIdx.x;
    const int rank = blockIdx.x & (CSIZE - 1);
    const int gcl = blockIdx.x >> 3;
    const int dir = gcl & 1;
    const int b0 = (gcl >> 1) * BC;

    const int half = tid >> 7;
    const int li = tid & 127;
    const int lane = li & 31;
    const int b = lane >> 3;                   // 0..3
    const int jl = (li >> 5) * 8 + (lane & 7); // 0..31
    const int jg = rank * JPC + jl;            // 0..255
    const int kbase = half * 32;               // in ulonglong2 units (x16B)

    const float* gx = &g_gx[0];
    float* out = layer ? dout : &g_out0[0];
    float* hn = write_hn ? dout + (size_t)NBATCH * S_LEN * OUTW : nullptr;

    // load W slice: 96 rows x 256 floats
    for (int i = tid; i < 96 * 64; i += SCTH) {
        int r = i >> 6, k4 = i & 63;
        int gi = r >> 5, jr = r & 31;
        *(float4*)&sW[(gi * JPC + jr) * HPAD + k4 * 4] =
            *(const float4*)&Whh[(size_t)(gi * HID + rank * JPC + jr) * HID + k4 * 4];
    }
    for (int i = tid; i < SH_FLOATS; i += SCTH) sh[i] = 0.f;

    const float bhr = __ldg(&bhh[jg]);
    const float bhz = __ldg(&bhh[HID + jg]);
    const float bhn = __ldg(&bhh[2 * HID + jg]);

    uint32_t sh_u32;
    {
        uint64_t tmp;
        asm("cvta.to.shared.u64 %0, %1;" : "=l"(tmp) : "l"(sh));
        sh_u32 = (uint32_t)tmp;
    }
    uint32_t peer[CSIZE];
#pragma unroll
    for (int r = 0; r < CSIZE; ++r)
        asm("mapa.shared::cluster.u32 %0, %1, %2;"
            : "=r"(peer[r]) : "r"(sh_u32), "r"(r));

    const float* gxbase = gx + (size_t)(b0 + b) * S_LEN * G3 + jg;
    float* outbase = out + ((size_t)(b0 + b) * S_LEN) * OUTW + dir * HID + jg;

    __syncthreads();
    asm volatile("barrier.cluster.arrive.aligned;" ::: "memory");
    asm volatile("barrier.cluster.wait.aligned;" ::: "memory");

    // gx prefetch for t = 0 (half 0 only consumes it)
    int tt0 = dir ? (S_LEN - 1) : 0;
    float gxr = __ldg(gxbase + (size_t)tt0 * G3);
    float gxz = __ldg(gxbase + (size_t)tt0 * G3 + HID);
    float gxn = __ldg(gxbase + (size_t)tt0 * G3 + 2 * HID);

    float hprev = 0.f;

    for (int t = 0; t < S_LEN; ++t) {
        const int tt = dir ? (S_LEN - 1 - t) : t;
        const int par = t & 1;

        // half-dot over 128 k-values, 3 gates, fully unrolled (deep LDS MLP)
        uint64_t ar0 = 0ull, ar1 = 0ull, az0 = 0ull, az1 = 0ull,
                 an0 = 0ull, an1 = 0ull;
        {
            const ulonglong2* hp =
                (const ulonglong2*)&sh[(par * BC + b) * HPAD] + kbase;
            const ulonglong2* wr =
                (const ulonglong2*)&sW[(0 * JPC + jl) * HPAD] + kbase;
            const ulonglong2* wz =
                (const ulonglong2*)&sW[(1 * JPC + jl) * HPAD] + kbase;
            const ulonglong2* wn =
                (const ulonglong2*)&sW[(2 * JPC + jl) * HPAD] + kbase;
#pragma unroll
            for (int k4 = 0; k4 < 32; ++k4) {
                ulonglong2 hv = hp[k4];
                ulonglong2 rv = wr[k4];
                ulonglong2 zv = wz[k4];
                ulonglong2 nv = wn[k4];
                fma2(ar0, hv.x, rv.x); fma2(ar1, hv.y, rv.y);
                fma2(az0, hv.x, zv.x); fma2(az1, hv.y, zv.y);
                fma2(an0, hv.x, nv.x); fma2(an1, hv.y, nv.y);
            }
        }
        float pr = upks(ar0) + upks(ar1);
        float pz = upks(az0) + upks(az1);
        float pn = upks(an0) + upks(an1);

        if (half == 1) sred[li] = make_float4(pr, pz, pn, 0.f);
        __syncthreads();

        float hnew = 0.f;
        if (half == 0) {
            float4 o = sred[li];
            float hr = pr + o.x + bhr;
            float hz = pz + o.y + bhz;
            float hv = pn + o.z + bhn;
            float rg = fsig(gxr + hr);
            float zg = fsig(gxz + hz);
            float ng = ftanh(gxn + rg * hv);
            hnew = (1.f - zg) * ng + zg * hprev;
            hprev = hnew;

            // scatter h' into every cluster CTA's sh[par^1][b][jg]
            const uint32_t off =
                (uint32_t)((((par ^ 1) * BC + b) * HPAD + jg) * 4);
#pragma unroll
            for (int r = 0; r < CSIZE; ++r)
                asm volatile("st.shared::cluster.f32 [%0], %1;"
                             :: "r"(peer[r] + off), "f"(hnew) : "memory");
        }

        asm volatile("barrier.cluster.arrive.aligned;" ::: "memory");

        if (half == 0) {
            outbase[(size_t)tt * OUTW] = hnew;
            if (t + 1 < S_LEN) {
                const int tn = dir ? (S_LEN - 2 - t) : (t + 1);
                const float* gp = gxbase + (size_t)tn * G3;
                gxr = __ldg(gp);
                gxz = __ldg(gp + HID);
                gxn = __ldg(gp + 2 * HID);
            } else if (hn) {
                hn[((size_t)(layer * 2 + dir) * NBATCH + b0 + b) * HID + jg] = hnew;
            }
        }

        asm volatile("barrier.cluster.wait.aligned;" ::: "memory");
    }
}

// ---------------------------------------------------------------------------
extern "C" void kernel_launch(void* const* d_in, const int* in_sizes, int n_in,
                              void* d_out, int out_size)
{
    const float* X     = (const float*)d_in[0];
    const float* Wih0  = (const float*)d_in[1];
    const float* Whh0  = (const float*)d_in[2];
    const float* bih0  = (const float*)d_in[3];
    const float* bhh0  = (const float*)d_in[4];
    const float* Wih1  = (const float*)d_in[5];
    const float* Whh1  = (const float*)d_in[6];
    const float* bih1  = (const float*)d_in[7];
    const float* bhh1  = (const float*)d_in[8];
    float* out = (float*)d_out;

    const long long need_hn =
        (long long)NBATCH * S_LEN * OUTW + 4LL * NBATCH * HID;
    int write_hn = ((long long)out_size >= need_hn) ? 1 : 0;

    cudaFuncSetAttribute(k_scan, cudaFuncAttributeMaxDynamicSharedMemorySize,
                         SMEM_BYTES);

    dim3 ggrid(512, 12);

    k_gemm<<<ggrid, 256>>>(X, Wih0, bih0, 256, 0);
    k_scan<<<128, SCTH, SMEM_BYTES>>>(Whh0, bhh0, out, 0, write_hn);

    k_gemm<<<ggrid, 256>>>(nullptr, Wih1, bih1, 512, 1);
    k_scan<<<128, SCTH, SMEM_BYTES>>>(Whh1, bhh1, out, 1, write_hn);
}

// round 12
// speedup vs baseline: 1.9422x; 1.9422x over previous
#include <cuda_runtime.h>
#include <cuda_bf16.h>
#include <cstdint>

// ---------------------------------------------------------------------------
// 2-layer bidirectional GRU. B=32, S=2048, D=256, H=256, gates=768.
//   gx = X @ W_ih^T + b_ih      (parallel GEMM)
//   step: gh = h @ W_hh^T + b_hh; r=sig(xr+hr) z=sig(xz+hz)
//         n=tanh(xn+r*hn); h' = (1-z)*n + z*h
// Scan: 16 groups (2 dirs x 8 batch-chunks of 4), each an 8-CTA cluster.
// CTA rank owns 32 j's (96 W_hh rows in smem). Thread (b,j) computes all
// three gate dots; h' scattered to all cluster CTAs via st.shared::cluster;
// one barrier.cluster per step. Dot FULLY UNROLLED with a high register cap
// (launch_bounds(128,1)) so ptxas batches ~16 LDS.128 in flight and hides
// the 29-cyc LDS latency that bound previous rounds.
// ---------------------------------------------------------------------------

#define S_LEN  2048
#define NBATCH 32
#define HID    256
#define G3     768
#define OUTW   512
#define BC     4          // batches per group
#define CSIZE  8          // CTAs per cluster (= slices per group)
#define JPC    32         // j's per CTA
#define HPAD   260        // padded row stride (floats); 1040B, 16B-aligned
#define SCTH   128

// smem layout (floats): W [3][JPC][HPAD] then h [2][BC][HPAD]
#define SW_FLOATS (3 * JPC * HPAD)          // 24960
#define SH_FLOATS (2 * BC * HPAD)           // 2080
#define SMEM_BYTES ((SW_FLOATS + SH_FLOATS) * 4)   // 108160

__device__ float g_gx[(size_t)NBATCH * S_LEN * G3];     // [b*S+s][768]
__device__ float g_out0[(size_t)NBATCH * S_LEN * OUTW]; // layer0 output

// ---- f32x2 helpers --------------------------------------------------------
__device__ __forceinline__ void fma2(uint64_t& d, uint64_t a, uint64_t b) {
    asm("fma.rn.f32x2 %0, %1, %2, %0;" : "+l"(d) : "l"(a), "l"(b));
}
__device__ __forceinline__ uint64_t pk(float lo, float hi) {
    uint64_t r; asm("mov.b64 %0, {%1, %2};" : "=l"(r) : "f"(lo), "f"(hi)); return r;
}
__device__ __forceinline__ float upks(uint64_t v) {
    float lo, hi; asm("mov.b64 {%0, %1}, %2;" : "=f"(lo), "=f"(hi) : "l"(v));
    return lo + hi;
}
__device__ __forceinline__ float fsig(float x) {
    return __fdividef(1.f, 1.f + __expf(-x));
}
__device__ __forceinline__ float ftanh(float x) {
    return 1.f - __fdividef(2.f, __expf(2.f * x) + 1.f);
}

// ---------------------------------------------------------------------------
// GEMM: C[m][n] = sum_k A[m][k]*W[n][k] + bias[n].  A:[65536][K], W:[768][K].
// Block 128(m) x 64(n), BK=8, 256 threads, 8x4 f32x2 accumulators.
// ---------------------------------------------------------------------------
__global__ void __launch_bounds__(256) k_gemm(
    const float* __restrict__ Aext, const float* __restrict__ W,
    const float* __restrict__ bias, int K, int useInternalA)
{
    __shared__ float As[8][132];
    __shared__ float Bs[8][68];

    const float* A = useInternalA ? &g_out0[0] : Aext;
    float* C = &g_gx[0];

    const int tid = threadIdx.x;
    const int bm = blockIdx.x, bn = blockIdx.y;
    const int tx = tid & 15, ty = tid >> 4;

    const int lr = tid >> 1, lq = (tid & 1) * 4;
    const float* Ap = A + (size_t)(bm * 128 + lr) * K + lq;
    const float* Bp = W + (size_t)(bn * 64 + (lr & 63)) * K + lq;
    const bool loadB = (tid < 128);

    uint64_t acc[8][4];
#pragma unroll
    for (int i = 0; i < 8; ++i)
#pragma unroll
        for (int j = 0; j < 4; ++j) acc[i][j] = 0ull;

    float4 av = *(const float4*)Ap;
    float4 bv = loadB ? *(const float4*)Bp : make_float4(0.f, 0.f, 0.f, 0.f);

    for (int kt = 0; kt < K; kt += 8) {
        __syncthreads();
        As[lq + 0][lr] = av.x; As[lq + 1][lr] = av.y;
        As[lq + 2][lr] = av.z; As[lq + 3][lr] = av.w;
        if (loadB) {
            Bs[lq + 0][lr] = bv.x; Bs[lq + 1][lr] = bv.y;
            Bs[lq + 2][lr] = bv.z; Bs[lq + 3][lr] = bv.w;
        }
        __syncthreads();
        if (kt + 8 < K) {
            av = *(const float4*)(Ap + kt + 8);
            if (loadB) bv = *(const float4*)(Bp + kt + 8);
        }
#pragma unroll
        for (int k2 = 0; k2 < 4; ++k2) {
            float4 aL0 = *(const float4*)&As[2 * k2][ty * 8];
            float4 aH0 = *(const float4*)&As[2 * k2][ty * 8 + 4];
            float4 aL1 = *(const float4*)&As[2 * k2 + 1][ty * 8];
            float4 aH1 = *(const float4*)&As[2 * k2 + 1][ty * 8 + 4];
            float4 b0  = *(const float4*)&Bs[2 * k2][tx * 4];
            float4 b1  = *(const float4*)&Bs[2 * k2 + 1][tx * 4];
            uint64_t am[8], bb[4];
            am[0] = pk(aL0.x, aL1.x); am[1] = pk(aL0.y, aL1.y);
            am[2] = pk(aL0.z, aL1.z); am[3] = pk(aL0.w, aL1.w);
            am[4] = pk(aH0.x, aH1.x); am[5] = pk(aH0.y, aH1.y);
            am[6] = pk(aH0.z, aH1.z); am[7] = pk(aH0.w, aH1.w);
            bb[0] = pk(b0.x, b1.x);   bb[1] = pk(b0.y, b1.y);
            bb[2] = pk(b0.z, b1.z);   bb[3] = pk(b0.w, b1.w);
#pragma unroll
            for (int i = 0; i < 8; ++i)
#pragma unroll
                for (int j = 0; j < 4; ++j) fma2(acc[i][j], am[i], bb[j]);
        }
    }

    const int n0 = bn * 64 + tx * 4;
    float4 b4 = *(const float4*)&bias[n0];
#pragma unroll
    for (int i = 0; i < 8; ++i) {
        size_t m = (size_t)bm * 128 + ty * 8 + i;
        float4 o;
        o.x = upks(acc[i][0]) + b4.x;
        o.y = upks(acc[i][1]) + b4.y;
        o.z = upks(acc[i][2]) + b4.z;
        o.w = upks(acc[i][3]) + b4.w;
        *(float4*)&C[m * G3 + n0] = o;
    }
}

// ---------------------------------------------------------------------------
// Cluster scan. Grid = 128 CTAs x 128 threads, cluster dims (8,1,1).
//   group gcl = bid>>3 (dir = gcl&1, b0 = (gcl>>1)*4), rank = bid&7.
// Thread: warp w = tid>>5 owns j in [w*8, w*8+8); lane: b = lane>>3,
// jj = lane&7 -> j_local = w*8+jj, jg = rank*32 + j_local.
// ---------------------------------------------------------------------------
__global__ void __launch_bounds__(SCTH, 1) __cluster_dims__(CSIZE, 1, 1)
k_scan(const float* __restrict__ Whh, const float* __restrict__ bhh,
       float* __restrict__ dout, int layer, int write_hn)
{
    extern __shared__ float smem[];
    float* sW = smem;                  // [3][JPC][HPAD]
    float* sh = smem + SW_FLOATS;      // [2][BC][HPAD]

    const int tid = threadIdx.x;
    const int rank = blockIdx.x & (CSIZE - 1);
    const int gcl = blockIdx.x >> 3;
    const int dir = gcl & 1;
    const int b0 = (gcl >> 1) * BC;

    const int w = tid >> 5, lane = tid & 31;
    const int b = lane >> 3;             // 0..3
    const int jl = w * 8 + (lane & 7);   // 0..31
    const int jg = rank * JPC + jl;      // 0..255

    const float* gx = &g_gx[0];
    float* out = layer ? dout : &g_out0[0];
    float* hn = write_hn ? dout + (size_t)NBATCH * S_LEN * OUTW : nullptr;

    // load W slice: 96 rows x 256 floats
    for (int i = tid; i < 96 * 64; i += SCTH) {
        int r = i >> 6, k4 = i & 63;
        int gi = r >> 5, jr = r & 31;
        *(float4*)&sW[(gi * JPC + jr) * HPAD + k4 * 4] =
            *(const float4*)&Whh[(size_t)(gi * HID + rank * JPC + jr) * HID + k4 * 4];
    }
    for (int i = tid; i < SH_FLOATS; i += SCTH) sh[i] = 0.f;

    const float bhr = __ldg(&bhh[jg]);
    const float bhz = __ldg(&bhh[HID + jg]);
    const float bhn = __ldg(&bhh[2 * HID + jg]);

    uint32_t sh_u32;
    {
        uint64_t tmp;
        asm("cvta.to.shared.u64 %0, %1;" : "=l"(tmp) : "l"(sh));
        sh_u32 = (uint32_t)tmp;
    }
    uint32_t peer[CSIZE];
#pragma unroll
    for (int r = 0; r < CSIZE; ++r)
        asm("mapa.shared::cluster.u32 %0, %1, %2;"
            : "=r"(peer[r]) : "r"(sh_u32), "r"(r));

    const float* gxbase = gx + (size_t)(b0 + b) * S_LEN * G3 + jg;
    float* outbase = out + ((size_t)(b0 + b) * S_LEN) * OUTW + dir * HID + jg;

    __syncthreads();
    asm volatile("barrier.cluster.arrive.aligned;" ::: "memory");
    asm volatile("barrier.cluster.wait.aligned;" ::: "memory");

    // gx prefetch for t = 0
    int tt0 = dir ? (S_LEN - 1) : 0;
    float gxr = __ldg(gxbase + (size_t)tt0 * G3);
    float gxz = __ldg(gxbase + (size_t)tt0 * G3 + HID);
    float gxn = __ldg(gxbase + (size_t)tt0 * G3 + 2 * HID);

    float hprev = 0.f;   // own element; carried in-register across steps

    for (int t = 0; t < S_LEN; ++t) {
        const int tt = dir ? (S_LEN - 1 - t) : t;
        const int par = t & 1;

        // three fused dots over k=256, FULLY UNROLLED (deep LDS batching)
        uint64_t ar0 = 0ull, ar1 = 0ull, az0 = 0ull, az1 = 0ull,
                 an0 = 0ull, an1 = 0ull;
        {
            const ulonglong2* __restrict__ hp =
                (const ulonglong2*)&sh[(par * BC + b) * HPAD];
            const ulonglong2* __restrict__ wr =
                (const ulonglong2*)&sW[(0 * JPC + jl) * HPAD];
            const ulonglong2* __restrict__ wz =
                (const ulonglong2*)&sW[(1 * JPC + jl) * HPAD];
            const ulonglong2* __restrict__ wn =
                (const ulonglong2*)&sW[(2 * JPC + jl) * HPAD];
#pragma unroll
            for (int k4 = 0; k4 < 64; ++k4) {
                ulonglong2 hv = hp[k4];
                ulonglong2 rv = wr[k4];
                ulonglong2 zv = wz[k4];
                ulonglong2 nv = wn[k4];
                fma2(ar0, hv.x, rv.x); fma2(ar1, hv.y, rv.y);
                fma2(az0, hv.x, zv.x); fma2(az1, hv.y, zv.y);
                fma2(an0, hv.x, nv.x); fma2(an1, hv.y, nv.y);
            }
        }
        float hr = upks(ar0) + upks(ar1) + bhr;
        float hz = upks(az0) + upks(az1) + bhz;
        float hv = upks(an0) + upks(an1) + bhn;

        float rg = fsig(gxr + hr);
        float zg = fsig(gxz + hz);
        float ng = ftanh(gxn + rg * hv);
        float hnew = (1.f - zg) * ng + zg * hprev;
        hprev = hnew;

        // scatter hnew into every cluster CTA's sh[par^1][b][jg]
        const uint32_t off = (uint32_t)((((par ^ 1) * BC + b) * HPAD + jg) * 4);
#pragma unroll
        for (int r = 0; r < CSIZE; ++r)
            asm volatile("st.shared::cluster.f32 [%0], %1;"
                         :: "r"(peer[r] + off), "f"(hnew) : "memory");

        // release our DSMEM stores; overlap global traffic with peers' arrival
        asm volatile("barrier.cluster.arrive.aligned;" ::: "memory");

        outbase[(size_t)tt * OUTW] = hnew;
        if (t + 1 < S_LEN) {
            const int tn = dir ? (S_LEN - 2 - t) : (t + 1);
            const float* gp = gxbase + (size_t)tn * G3;
            gxr = __ldg(gp);
            gxz = __ldg(gp + HID);
            gxn = __ldg(gp + 2 * HID);
        } else if (hn) {
            hn[((size_t)(layer * 2 + dir) * NBATCH + b0 + b) * HID + jg] = hnew;
        }

        asm volatile("barrier.cluster.wait.aligned;" ::: "memory");
    }
}

// ---------------------------------------------------------------------------
extern "C" void kernel_launch(void* const* d_in, const int* in_sizes, int n_in,
                              void* d_out, int out_size)
{
    const float* X     = (const float*)d_in[0];
    const float* Wih0  = (const float*)d_in[1];
    const float* Whh0  = (const float*)d_in[2];
    const float* bih0  = (const float*)d_in[3];
    const float* bhh0  = (const float*)d_in[4];
    const float* Wih1  = (const float*)d_in[5];
    const float* Whh1  = (const float*)d_in[6];
    const float* bih1  = (const float*)d_in[7];
    const float* bhh1  = (const float*)d_in[8];
    float* out = (float*)d_out;

    const long long need_hn =
        (long long)NBATCH * S_LEN * OUTW + 4LL * NBATCH * HID;
    int write_hn = ((long long)out_size >= need_hn) ? 1 : 0;

    cudaFuncSetAttribute(k_scan, cudaFuncAttributeMaxDynamicSharedMemorySize,
                         SMEM_BYTES);

    dim3 ggrid(512, 12);

    k_gemm<<<ggrid, 256>>>(X, Wih0, bih0, 256, 0);
    k_scan<<<128, SCTH, SMEM_BYTES>>>(Whh0, bhh0, out, 0, write_hn);

    k_gemm<<<ggrid, 256>>>(nullptr, Wih1, bih1, 512, 1);
    k_scan<<<128, SCTH, SMEM_BYTES>>>(Whh1, bhh1, out, 1, write_hn);
}